// round 6
// baseline (speedup 1.0000x reference)
#include <cuda_runtime.h>
#include <cstdint>

// ---------------------------------------------------------------------------
// fp4 (bitsandbytes) dequant + GEMV:  y[4, M] = x[4, N] @ W[M, N]^T + bias
//   qweight: numel/2 int32, each holding ONE byte (two nibbles, hi first)
//   absmax : per-64-element block scale; code: 16-entry codebook
//
// Lane l owns int32 pair (2i, 2i+1), i = step*32 + lane  ->  n = 4i..4i+3.
//   q:  LDG.64 per row, lanes consecutive (coalesced)
//   x:  LDG.128 float4 per batch, lanes consecutive (coalesced)
//   am: one scale covers the lane's whole 4-n window (block = i>>4)
// Decode: register-resident 16-entry codebook via __shfl (conflict-free).
// Scale folding: accumulate unscaled dot-product t per (row, step), then
// one packed FMA by the absmax scale. 4 rows/warp, 4 warps/block, N split 2.
// ---------------------------------------------------------------------------

constexpr int MD = 8192, ND = 8192;
constexpr int NSPLIT = 2;
constexpr int NHALF  = ND / NSPLIT;       // 4096 n per block
constexpr int STEPS  = NHALF / 128;       // 32 steps of 128 n
constexpr int RW = 4;                     // rows per warp
constexpr int WPB = 4;                    // warps per block (128 threads)
constexpr int RPB = RW * WPB;             // 16 rows per block

__device__ float g_part[NSPLIT * 4 * MD];   // [split][batch][row]

static __device__ __forceinline__ unsigned long long pk2(float lo, float hi) {
    unsigned long long r;
    asm("mov.b64 %0, {%1, %2};" : "=l"(r) : "f"(lo), "f"(hi));
    return r;
}
static __device__ __forceinline__ void up2(unsigned long long v, float& lo, float& hi) {
    asm("mov.b64 {%0, %1}, %2;" : "=f"(lo), "=f"(hi) : "l"(v));
}
static __device__ __forceinline__ unsigned long long f2fma(unsigned long long a,
                                                           unsigned long long b,
                                                           unsigned long long c) {
    unsigned long long d;
    asm("fma.rn.f32x2 %0, %1, %2, %3;" : "=l"(d) : "l"(a), "l"(b), "l"(c));
    return d;
}
static __device__ __forceinline__ unsigned long long f2mul(unsigned long long a,
                                                           unsigned long long b) {
    unsigned long long d;
    asm("mul.rn.f32x2 %0, %1, %2;" : "=l"(d) : "l"(a), "l"(b));
    return d;
}
static __device__ __forceinline__ unsigned long long f2add(unsigned long long a,
                                                           unsigned long long b) {
    unsigned long long d;
    asm("add.rn.f32x2 %0, %1, %2;" : "=l"(d) : "l"(a), "l"(b));
    return d;
}

__global__ void __launch_bounds__(128, 8)
fp4_main(const float* __restrict__ x, const int* __restrict__ qw,
         const float* __restrict__ am, const float* __restrict__ code)
{
    const int lane = threadIdx.x & 31;
    const int wid  = threadIdx.x >> 5;
    const int split = blockIdx.x;              // 0 or 1
    const int row0  = blockIdx.y * RPB + wid * RW;
    const int n0    = split * NHALF;

    // Register-resident codebook: lane l holds code[l & 15]; decode via shfl.
    const float creg = code[lane & 15];

    // Per-row streams for this N-half.
    const int2*  q0  = reinterpret_cast<const int2*>(qw) + row0 * (ND / 4)
                       + split * (NHALF / 4);
    const float* am0 = am + row0 * (ND / 64) + split * (NHALF / 64);
    const float4* x0 = reinterpret_cast<const float4*>(x + 0 * ND + n0);
    const float4* x1 = reinterpret_cast<const float4*>(x + 1 * ND + n0);
    const float4* x2 = reinterpret_cast<const float4*>(x + 2 * ND + n0);
    const float4* x3 = reinterpret_cast<const float4*>(x + 3 * ND + n0);

    unsigned long long a01[RW] = {0, 0, 0, 0};
    unsigned long long a23[RW] = {0, 0, 0, 0};

#pragma unroll 2
    for (int step = 0; step < STEPS; ++step) {
        const int i = step * 32 + lane;        // float4 / int2 index; n = 4i..4i+3

        // Issue all loads up front for MLP.
        const int2 q[RW] = {
            __ldg(&q0[0 * (ND / 4) + i]),
            __ldg(&q0[1 * (ND / 4) + i]),
            __ldg(&q0[2 * (ND / 4) + i]),
            __ldg(&q0[3 * (ND / 4) + i]),
        };
        const float s[RW] = {
            __ldg(&am0[0 * (ND / 64) + (i >> 4)]),
            __ldg(&am0[1 * (ND / 64) + (i >> 4)]),
            __ldg(&am0[2 * (ND / 64) + (i >> 4)]),
            __ldg(&am0[3 * (ND / 64) + (i >> 4)]),
        };
        const float4 v0 = __ldg(&x0[i]);
        const float4 v1 = __ldg(&x1[i]);
        const float4 v2 = __ldg(&x2[i]);
        const float4 v3 = __ldg(&x3[i]);

        // Batch-pair packed x for the 4 n positions.
        const unsigned long long p01[4] = {
            pk2(v0.x, v1.x), pk2(v0.y, v1.y), pk2(v0.z, v1.z), pk2(v0.w, v1.w)
        };
        const unsigned long long p23[4] = {
            pk2(v2.x, v3.x), pk2(v2.y, v3.y), pk2(v2.z, v3.z), pk2(v2.w, v3.w)
        };

#pragma unroll
        for (int r = 0; r < RW; r++) {
            // Two packed bytes -> 4 codebook values (n = 4i .. 4i+3).
            const float c0 = __shfl_sync(0xffffffffu, creg, q[r].x >> 4);
            const float c1 = __shfl_sync(0xffffffffu, creg, q[r].x & 15);
            const float c2 = __shfl_sync(0xffffffffu, creg, q[r].y >> 4);
            const float c3 = __shfl_sync(0xffffffffu, creg, q[r].y & 15);
            const unsigned long long cc0 = pk2(c0, c0);
            const unsigned long long cc1 = pk2(c1, c1);
            const unsigned long long cc2 = pk2(c2, c2);
            const unsigned long long cc3 = pk2(c3, c3);

            // Unscaled dot-product over this lane's 4-n window.
            unsigned long long t01 = f2mul(cc0, p01[0]);
            unsigned long long t23 = f2mul(cc0, p23[0]);
            t01 = f2fma(cc1, p01[1], t01);
            t23 = f2fma(cc1, p23[1], t23);
            t01 = f2fma(cc2, p01[2], t01);
            t23 = f2fma(cc2, p23[2], t23);
            t01 = f2fma(cc3, p01[3], t01);
            t23 = f2fma(cc3, p23[3], t23);

            // Fold the (single) absmax scale once.
            const unsigned long long ss = pk2(s[r], s[r]);
            a01[r] = f2fma(t01, ss, a01[r]);
            a23[r] = f2fma(t23, ss, a23[r]);
        }
    }

    // Butterfly reduction over lanes (packed f32x2 adds).
#pragma unroll
    for (int r = 0; r < RW; r++) {
#pragma unroll
        for (int off = 16; off > 0; off >>= 1) {
            a01[r] = f2add(a01[r], __shfl_xor_sync(0xffffffffu, a01[r], off));
            a23[r] = f2add(a23[r], __shfl_xor_sync(0xffffffffu, a23[r], off));
        }
    }

#pragma unroll
    for (int r = 0; r < RW; r++) {
        if (lane == r) {
            const int row = row0 + r;
            float y0, y1, y2, y3;
            up2(a01[r], y0, y1);
            up2(a23[r], y2, y3);
            g_part[(split * 4 + 0) * MD + row] = y0;
            g_part[(split * 4 + 1) * MD + row] = y1;
            g_part[(split * 4 + 2) * MD + row] = y2;
            g_part[(split * 4 + 3) * MD + row] = y3;
        }
    }
}

__global__ void __launch_bounds__(256)
fp4_reduce(const float* __restrict__ bias, float* __restrict__ out)
{
    // i4 indexes groups of 4 consecutive outputs (same batch, consecutive rows).
    const int i4 = blockIdx.x * 256 + threadIdx.x;
    if (i4 >= (4 * MD) / 4) return;
    const int i   = i4 * 4;
    const int row = i & (MD - 1);
    const float4 p0 = *reinterpret_cast<const float4*>(g_part + 0 * 4 * MD + i);
    const float4 p1 = *reinterpret_cast<const float4*>(g_part + 1 * 4 * MD + i);
    const float4 bb = *reinterpret_cast<const float4*>(bias + row);
    float4 o;
    o.x = p0.x + p1.x + bb.x;
    o.y = p0.y + p1.y + bb.y;
    o.z = p0.z + p1.z + bb.z;
    o.w = p0.w + p1.w + bb.w;
    *reinterpret_cast<float4*>(out + i) = o;
}

extern "C" void kernel_launch(void* const* d_in, const int* in_sizes, int n_in,
                              void* d_out, int out_size)
{
    const float* x    = (const float*)d_in[0];
    const int*   qw   = (const int*)d_in[1];
    const float* am   = (const float*)d_in[2];
    const float* code = (const float*)d_in[3];
    const float* bias = (const float*)d_in[4];
    float*       out  = (float*)d_out;

    dim3 grid(NSPLIT, MD / RPB);              // (2, 512) = 1024 blocks
    fp4_main<<<grid, WPB * 32>>>(x, qw, am, code);
    fp4_reduce<<<((4 * MD) / 4 + 255) / 256, 256>>>(bias, out);
}